// round 8
// baseline (speedup 1.0000x reference)
#include <cuda_runtime.h>
#include <cuda_fp16.h>
#include <cuda_bf16.h>
#include <math.h>
#include <cstdint>

#define NN      50000
#define E_BASE  800000
#define E_TOT   850000   // + self loops
#define FEAT    128
#define HID     128
#define NHEAD   8
#define GN      144      // GEMM output cols: 128 h + 8 alpha_src + 8 alpha_dst

// ---------------- scratch (device globals; no allocation) ----------------
__device__ __half g_h [NN * HID];   // fp16 gather table
__device__ float  g_x2[NN * HID];   // layer-1 output (fp32)
__device__ float  g_as[NN * NHEAD];
__device__ float  g_ad[NN * NHEAD];
__device__ float  g_wa[128 * 16];   // folded attention weights [k][0..7]=src, [8..15]=dst
__device__ int    g_cnt[NN];
__device__ int    g_off[NN + 1];
__device__ int    g_rank[E_TOT];
__device__ int    g_csr[E_TOT];

// ---------------- CSR build ----------------
__global__ void zero_kernel() {
    int i = blockIdx.x * blockDim.x + threadIdx.x;
    if (i < NN) g_cnt[i] = 0;
}
__global__ void count_kernel(const int* __restrict__ ei) {
    int i = blockIdx.x * blockDim.x + threadIdx.x;
    if (i >= E_TOT) return;
    int d = (i < E_BASE) ? ei[E_BASE + i] : (i - E_BASE);
    g_rank[i] = atomicAdd(&g_cnt[d], 1);
}
#define SCAN_CHUNK 49
__global__ void scan_kernel() {
    __shared__ int warp_sums[32];
    int t = threadIdx.x, lane = t & 31, w = t >> 5;
    int base = t * SCAN_CHUNK;
    int local = 0;
    #pragma unroll 7
    for (int j = 0; j < SCAN_CHUNK; ++j) { int i = base + j; if (i < NN) local += g_cnt[i]; }
    int x = local;
    #pragma unroll
    for (int o = 1; o < 32; o <<= 1) { int y = __shfl_up_sync(~0u, x, o); if (lane >= o) x += y; }
    if (lane == 31) warp_sums[w] = x;
    __syncthreads();
    if (w == 0) {
        int s = warp_sums[lane];
        #pragma unroll
        for (int o = 1; o < 32; o <<= 1) { int y = __shfl_up_sync(~0u, s, o); if (lane >= o) s += y; }
        warp_sums[lane] = s;
    }
    __syncthreads();
    int excl = x - local + ((w > 0) ? warp_sums[w - 1] : 0);
    int run = excl;
    #pragma unroll 7
    for (int j = 0; j < SCAN_CHUNK; ++j) { int i = base + j; if (i < NN) { g_off[i] = run; run += g_cnt[i]; } }
    if (t == 1023) g_off[NN] = run;
}
__global__ void scatter_kernel(const int* __restrict__ ei) {
    int i = blockIdx.x * blockDim.x + threadIdx.x;
    if (i >= E_TOT) return;
    int s, d;
    if (i < E_BASE) { s = ei[i]; d = ei[E_BASE + i]; }
    else            { s = d = i - E_BASE; }
    g_csr[g_off[d] + g_rank[i]] = s;
}

// ---------------- wa = W @ a (per head) ----------------
__global__ void wa_kernel(const float* __restrict__ W,
                          const float* __restrict__ a_src,
                          const float* __restrict__ a_dst) {
    __shared__ float as[128], ad[128];
    int t = threadIdx.x;
    as[t] = a_src[t]; ad[t] = a_dst[t];
    __syncthreads();
    int k = t;
    #pragma unroll
    for (int h = 0; h < 8; h++) {
        float s = 0.f, d = 0.f;
        #pragma unroll
        for (int c = 0; c < 16; c++) {
            float w = W[k * 128 + h * 16 + c];
            s += w * as[h * 16 + c];
            d += w * ad[h * 16 + c];
        }
        g_wa[k * 16 + h]     = s;
        g_wa[k * 16 + 8 + h] = d;
    }
}

// ---------------- tensor-core GEMM via mma.sync (arch-portable HMMA) --------
// C[128 x 144] = x @ W_ext with ~fp32 precision via bf16 hi/lo 3-term scheme:
//   storage: A = [x_hi | x_lo] (K=256), B = [Wt_hi | Wt_lo] (K=256)
//   24 k16-steps remapped so sum = hi*hi + lo*hi + hi*lo  (lo*lo ~ 2^-18, dropped)
#define AST 264                        // smem stride in halves (528 B, conflict-free)
#define SM_A_BYTES (128 * AST * 2)     // 67584
#define SM_B_BYTES (GN  * AST * 2)     // 76032
#define TCG_SMEM   (SM_A_BYTES + SM_B_BYTES)   // 143616 B

__device__ __forceinline__ uint32_t smem_u32(const void* p) {
    uint32_t a;
    asm("{ .reg .u64 t; cvta.to.shared.u64 t, %1; cvt.u32.u64 %0, t; }" : "=r"(a) : "l"(p));
    return a;
}
__device__ __forceinline__ void ldm4(uint32_t* r, uint32_t addr) {
    asm volatile("ldmatrix.sync.aligned.m8n8.x4.shared.b16 {%0,%1,%2,%3}, [%4];"
                 : "=r"(r[0]), "=r"(r[1]), "=r"(r[2]), "=r"(r[3]) : "r"(addr));
}
__device__ __forceinline__ void ldm2(uint32_t* r, uint32_t addr) {
    asm volatile("ldmatrix.sync.aligned.m8n8.x2.shared.b16 {%0,%1}, [%2];"
                 : "=r"(r[0]), "=r"(r[1]) : "r"(addr));
}
__device__ __forceinline__ void mma16816(float* c, const uint32_t* a, const uint32_t* b) {
    asm volatile(
        "mma.sync.aligned.m16n8k16.row.col.f32.bf16.bf16.f32 "
        "{%0,%1,%2,%3}, {%4,%5,%6,%7}, {%8,%9}, {%0,%1,%2,%3};"
        : "+f"(c[0]), "+f"(c[1]), "+f"(c[2]), "+f"(c[3])
        : "r"(a[0]), "r"(a[1]), "r"(a[2]), "r"(a[3]), "r"(b[0]), "r"(b[1]));
}
__device__ __forceinline__ void split_bf16(float v, __nv_bfloat16& hi, __nv_bfloat16& lo) {
    hi = __float2bfloat16(v);
    lo = __float2bfloat16(v - __bfloat162float(hi));
}

__global__ void __launch_bounds__(256, 1)
tc_gemm_kernel(const float* __restrict__ X, const float* __restrict__ W) {
    extern __shared__ char smem[];
    __nv_bfloat16* As = (__nv_bfloat16*)smem;                  // [128][AST] (hi k0..127, lo 128..255)
    __nv_bfloat16* Bs = (__nv_bfloat16*)(smem + SM_A_BYTES);   // [144][AST]

    int tid = threadIdx.x;          // 256
    int row0 = blockIdx.x * 128;

    // ---- prologue: fill smem with bf16 hi/lo splits ----
    // A: X rows [row0, row0+128)
    for (int i = tid; i < 128 * 32; i += 256) {
        int r = i >> 5, q = i & 31;
        int k = q * 4;
        int gr = row0 + r;
        float4 v = make_float4(0.f, 0.f, 0.f, 0.f);
        if (gr < NN) v = *(const float4*)(X + gr * FEAT + k);
        __nv_bfloat16 h0, h1, h2, h3, l0, l1, l2, l3;
        split_bf16(v.x, h0, l0); split_bf16(v.y, h1, l1);
        split_bf16(v.z, h2, l2); split_bf16(v.w, h3, l3);
        __nv_bfloat16* row = As + r * AST;
        *(__nv_bfloat162*)(row + k)           = __nv_bfloat162(h0, h1);
        *(__nv_bfloat162*)(row + k + 2)       = __nv_bfloat162(h2, h3);
        *(__nv_bfloat162*)(row + 128 + k)     = __nv_bfloat162(l0, l1);
        *(__nv_bfloat162*)(row + 128 + k + 2) = __nv_bfloat162(l2, l3);
    }
    // B rows 0..127 from W (transposed: Bs[c][k] = W[k*128+c])
    for (int i = tid; i < 128 * 32; i += 256) {
        int k = i >> 5, q = i & 31;
        int c = q * 4;
        float4 v = *(const float4*)(W + k * 128 + c);
        __nv_bfloat16 hi, lo;
        split_bf16(v.x, hi, lo); Bs[(c + 0) * AST + k] = hi; Bs[(c + 0) * AST + 128 + k] = lo;
        split_bf16(v.y, hi, lo); Bs[(c + 1) * AST + k] = hi; Bs[(c + 1) * AST + 128 + k] = lo;
        split_bf16(v.z, hi, lo); Bs[(c + 2) * AST + k] = hi; Bs[(c + 2) * AST + 128 + k] = lo;
        split_bf16(v.w, hi, lo); Bs[(c + 3) * AST + k] = hi; Bs[(c + 3) * AST + 128 + k] = lo;
    }
    // B rows 128..143 from g_wa (Bs[128+j][k] = g_wa[k*16+j])
    for (int i = tid; i < 128 * 16; i += 256) {
        int k = i >> 4, j = i & 15;
        __nv_bfloat16 hi, lo;
        split_bf16(g_wa[i], hi, lo);
        Bs[(128 + j) * AST + k] = hi;
        Bs[(128 + j) * AST + 128 + k] = lo;
    }
    __syncthreads();

    // ---- mainloop: 24 k16-steps, segment-remapped hi/lo passes ----
    int wid = tid >> 5, lane = tid & 31;
    int warp_m = wid & 3;             // 4 warps in M
    int warp_n = wid >> 2;            // 2 warps in N
    int m_base = warp_m * 32;
    int n_base = warp_n * 72;

    uint32_t sb = smem_u32(smem);
    uint32_t a_addr = sb + (uint32_t)(m_base + (lane & 15)) * (AST * 2)
                         + (uint32_t)((lane >> 4) << 3) * 2;
    uint32_t b_addr = sb + SM_A_BYTES
                         + (uint32_t)(n_base + (lane & 7)) * (AST * 2)
                         + (uint32_t)(((lane >> 3) & 1) << 3) * 2;

    float c[2][9][4];
    #pragma unroll
    for (int i = 0; i < 2; i++)
        #pragma unroll
        for (int j = 0; j < 9; j++)
            #pragma unroll
            for (int q = 0; q < 4; q++) c[i][j][q] = 0.f;

    // ks 0-7:  A hi (k=ks)    x B hi (k=ks)
    // ks 8-15: A lo (k=ks)    x B hi (k=ks-8)
    // ks 16-23:A hi (k=ks-16) x B lo (k=ks-8)
    #pragma unroll
    for (int ks = 0; ks < 24; ++ks) {
        int ak = (ks < 16) ? ks : (ks - 16);
        int bk = (ks < 8)  ? ks : (ks - 8);
        uint32_t akoff = (uint32_t)ak * 32;   // 16 halves = 32 bytes
        uint32_t bkoff = (uint32_t)bk * 32;
        uint32_t a0[4], a1[4];
        ldm4(a0, a_addr + akoff);
        ldm4(a1, a_addr + akoff + 16 * (AST * 2));
        uint32_t b[9][2];
        #pragma unroll
        for (int j = 0; j < 9; ++j)
            ldm2(b[j], b_addr + bkoff + (uint32_t)j * 8 * (AST * 2));
        #pragma unroll
        for (int j = 0; j < 9; ++j) {
            mma16816(c[0][j], a0, b[j]);
            mma16816(c[1][j], a1, b[j]);
        }
    }

    // ---- epilogue: direct register -> global ----
    int r_lane = lane >> 2;
    int c_lane = (lane & 3) * 2;
    #pragma unroll
    for (int i = 0; i < 2; ++i) {
        int gr0 = row0 + m_base + i * 16 + r_lane;
        int gr1 = gr0 + 8;
        #pragma unroll
        for (int j = 0; j < 9; ++j) {
            int nc = n_base + j * 8 + c_lane;
            float v00 = c[i][j][0], v01 = c[i][j][1];
            float v10 = c[i][j][2], v11 = c[i][j][3];
            if (nc < 128) {
                if (gr0 < NN) {
                    __half2 p = __halves2half2(__float2half_rn(v00), __float2half_rn(v01));
                    *(__half2*)(g_h + gr0 * 128 + nc) = p;
                }
                if (gr1 < NN) {
                    __half2 p = __halves2half2(__float2half_rn(v10), __float2half_rn(v11));
                    *(__half2*)(g_h + gr1 * 128 + nc) = p;
                }
            } else {
                int cc = nc - 128;   // 0..15, even
                if (cc < 8) {
                    if (gr0 < NN) { g_as[gr0 * 8 + cc] = v00; g_as[gr0 * 8 + cc + 1] = v01; }
                    if (gr1 < NN) { g_as[gr1 * 8 + cc] = v10; g_as[gr1 * 8 + cc + 1] = v11; }
                } else {
                    int dd = cc - 8;
                    if (gr0 < NN) { g_ad[gr0 * 8 + dd] = v00; g_ad[gr0 * 8 + dd + 1] = v01; }
                    if (gr1 < NN) { g_ad[gr1 * 8 + dd] = v10; g_ad[gr1 * 8 + dd + 1] = v11; }
                }
            }
        }
    }
}

// ---------------- fused GAT aggregation: warp per dst node (fp16 gather) -----
__global__ void msg_kernel(const float* __restrict__ bias, float* __restrict__ out) {
    int gwarp = (blockIdx.x * blockDim.x + threadIdx.x) >> 5;
    int lane = threadIdx.x & 31;
    if (gwarp >= NN) return;
    int d = gwarp;
    int head = lane >> 2;
    float ad_h = g_ad[d * 8 + head];
    int beg = g_off[d], end = g_off[d + 1];
    int col = lane << 2;

    float4 acc = make_float4(0.f, 0.f, 0.f, 0.f);
    float ssum = 0.f;
    for (int i = beg; i < end; ++i) {
        int s = g_csr[i];
        float as_h = __ldg(&g_as[s * 8 + head]);
        float v = as_h + ad_h;
        v = (v > 0.f) ? v : 0.2f * v;
        float e = __expf(v);
        uint2 raw = *(const uint2*)(g_h + s * 128 + col);
        float2 f0 = __half22float2(*(__half2*)&raw.x);
        float2 f1 = __half22float2(*(__half2*)&raw.y);
        acc.x += e * f0.x;
        acc.y += e * f0.y;
        acc.z += e * f1.x;
        acc.w += e * f1.y;
        ssum += e;
    }
    float inv = 1.f / (ssum + 1e-16f);
    float4 bb = *(const float4*)(bias + col);
    float4 o;
    float t;
    t = acc.x * inv + bb.x; o.x = (t > 0.f) ? t : expm1f(t);
    t = acc.y * inv + bb.y; o.y = (t > 0.f) ? t : expm1f(t);
    t = acc.z * inv + bb.z; o.z = (t > 0.f) ? t : expm1f(t);
    t = acc.w * inv + bb.w; o.w = (t > 0.f) ? t : expm1f(t);
    *(float4*)(out + d * 128 + col) = o;
}

// ---------------- launch ----------------
extern "C" void kernel_launch(void* const* d_in, const int* in_sizes, int n_in,
                              void* d_out, int out_size) {
    const float* x   = (const float*)d_in[0];
    const int*   ei  = (const int*)  d_in[1];
    const float* W1  = (const float*)d_in[2];
    const float* as1 = (const float*)d_in[3];
    const float* ad1 = (const float*)d_in[4];
    const float* b1  = (const float*)d_in[5];
    const float* W2  = (const float*)d_in[6];
    const float* as2 = (const float*)d_in[7];
    const float* ad2 = (const float*)d_in[8];
    const float* b2  = (const float*)d_in[9];
    float* out = (float*)d_out;

    cudaFuncSetAttribute(tc_gemm_kernel,
                         cudaFuncAttributeMaxDynamicSharedMemorySize, TCG_SMEM);

    void* p_x2 = nullptr;
    cudaGetSymbolAddress(&p_x2, g_x2);
    float* x2 = (float*)p_x2;

    int gemm_grid = (NN + 127) / 128;         // 391
    int msg_grid  = (NN * 32 + 255) / 256;

    // layer 1  (tc_gemm is 4th launch -> ncu capture target)
    wa_kernel     <<<1, 128>>>(W1, as1, ad1);                 // 1
    zero_kernel   <<<(NN + 255) / 256, 256>>>();              // 2
    count_kernel  <<<(E_TOT + 255) / 256, 256>>>(ei);         // 3
    tc_gemm_kernel<<<gemm_grid, 256, TCG_SMEM>>>(x, W1);      // 4 <- ncu
    scan_kernel   <<<1, 1024>>>();                            // 5
    scatter_kernel<<<(E_TOT + 255) / 256, 256>>>(ei);         // 6
    msg_kernel    <<<msg_grid, 256>>>(b1, x2);                // 7

    // layer 2
    wa_kernel     <<<1, 128>>>(W2, as2, ad2);                 // 8
    tc_gemm_kernel<<<gemm_grid, 256, TCG_SMEM>>>(x2, W2);     // 9
    msg_kernel    <<<msg_grid, 256>>>(b2, out);               // 10
}

// round 9
// speedup vs baseline: 1.3111x; 1.3111x over previous
#include <cuda_runtime.h>
#include <cuda_fp16.h>
#include <cuda_bf16.h>
#include <math.h>
#include <cstdint>

#define NN      50000
#define E_BASE  800000
#define E_TOT   850000   // + self loops
#define FEAT    128
#define HID     128
#define NHEAD   8
#define GN      144      // GEMM output cols: 128 h + 8 alpha_src + 8 alpha_dst

// ---------------- scratch (device globals; no allocation) ----------------
__device__ __half        g_h [NN * HID];   // fp16 gather table
__device__ float         g_x2[NN * HID];   // layer-1 output (fp32)
__device__ float         g_as[NN * NHEAD];
__device__ float         g_ad[NN * NHEAD];
__device__ float         g_wa[128 * 16];   // folded attention weights
__device__ __nv_bfloat16 g_wb[GN * 256];   // W^T ext, [c][k]: k 0..127 hi, 128..255 lo
__device__ int           g_cnt[NN];
__device__ int           g_off[NN + 1];
__device__ int           g_rank[E_TOT];
__device__ int           g_csr[E_TOT];

// ---------------- CSR build ----------------
__global__ void zero_kernel() {
    int i = blockIdx.x * blockDim.x + threadIdx.x;
    if (i < NN) g_cnt[i] = 0;
}
__global__ void count_kernel(const int* __restrict__ ei) {
    int i = blockIdx.x * blockDim.x + threadIdx.x;
    if (i >= E_TOT) return;
    int d = (i < E_BASE) ? ei[E_BASE + i] : (i - E_BASE);
    g_rank[i] = atomicAdd(&g_cnt[d], 1);
}
#define SCAN_CHUNK 49
__global__ void scan_kernel() {
    __shared__ int warp_sums[32];
    int t = threadIdx.x, lane = t & 31, w = t >> 5;
    int base = t * SCAN_CHUNK;
    int local = 0;
    #pragma unroll 7
    for (int j = 0; j < SCAN_CHUNK; ++j) { int i = base + j; if (i < NN) local += g_cnt[i]; }
    int x = local;
    #pragma unroll
    for (int o = 1; o < 32; o <<= 1) { int y = __shfl_up_sync(~0u, x, o); if (lane >= o) x += y; }
    if (lane == 31) warp_sums[w] = x;
    __syncthreads();
    if (w == 0) {
        int s = warp_sums[lane];
        #pragma unroll
        for (int o = 1; o < 32; o <<= 1) { int y = __shfl_up_sync(~0u, s, o); if (lane >= o) s += y; }
        warp_sums[lane] = s;
    }
    __syncthreads();
    int excl = x - local + ((w > 0) ? warp_sums[w - 1] : 0);
    int run = excl;
    #pragma unroll 7
    for (int j = 0; j < SCAN_CHUNK; ++j) { int i = base + j; if (i < NN) { g_off[i] = run; run += g_cnt[i]; } }
    if (t == 1023) g_off[NN] = run;
}
__global__ void scatter_kernel(const int* __restrict__ ei) {
    int i = blockIdx.x * blockDim.x + threadIdx.x;
    if (i >= E_TOT) return;
    int s, d;
    if (i < E_BASE) { s = ei[i]; d = ei[E_BASE + i]; }
    else            { s = d = i - E_BASE; }
    g_csr[g_off[d] + g_rank[i]] = s;
}

// ---------------- wa = W @ a (per head) ----------------
__global__ void wa_kernel(const float* __restrict__ W,
                          const float* __restrict__ a_src,
                          const float* __restrict__ a_dst) {
    __shared__ float as[128], ad[128];
    int t = threadIdx.x;
    as[t] = a_src[t]; ad[t] = a_dst[t];
    __syncthreads();
    int k = t;
    #pragma unroll
    for (int h = 0; h < 8; h++) {
        float s = 0.f, d = 0.f;
        #pragma unroll
        for (int c = 0; c < 16; c++) {
            float w = W[k * 128 + h * 16 + c];
            s += w * as[h * 16 + c];
            d += w * ad[h * 16 + c];
        }
        g_wa[k * 16 + h]     = s;
        g_wa[k * 16 + 8 + h] = d;
    }
}

__device__ __forceinline__ void split_bf16(float v, __nv_bfloat16& hi, __nv_bfloat16& lo) {
    hi = __float2bfloat16(v);
    lo = __float2bfloat16(v - __bfloat162float(hi));
}

// precompute W^T extended hi/lo table (per layer; depends on g_wa)
__global__ void wsplit_kernel(const float* __restrict__ W) {
    int i = blockIdx.x * blockDim.x + threadIdx.x;   // 144*128
    if (i >= GN * 128) return;
    int c = i >> 7, k = i & 127;
    float v = (c < 128) ? W[k * 128 + c] : g_wa[k * 16 + (c - 128)];
    __nv_bfloat16 hi, lo;
    split_bf16(v, hi, lo);
    g_wb[c * 256 + k]       = hi;
    g_wb[c * 256 + 128 + k] = lo;
}

// ---------------- tensor-core GEMM via mma.sync (arch-portable HMMA) --------
// C[128 x 144] = x @ W_ext, ~fp32 precision: 3 passes hi*hi + lo*hi + hi*lo.
#define AST 264                        // smem stride in halves (528 B)
#define SM_A_BYTES (128 * AST * 2)     // 67584
#define SM_B_BYTES (GN  * AST * 2)     // 76032
#define TCG_SMEM   (SM_A_BYTES + SM_B_BYTES)   // 143616 B

__device__ __forceinline__ uint32_t smem_u32(const void* p) {
    uint32_t a;
    asm("{ .reg .u64 t; cvta.to.shared.u64 t, %1; cvt.u32.u64 %0, t; }" : "=r"(a) : "l"(p));
    return a;
}
__device__ __forceinline__ void ldm4(uint32_t* r, uint32_t addr) {
    asm volatile("ldmatrix.sync.aligned.m8n8.x4.shared.b16 {%0,%1,%2,%3}, [%4];"
                 : "=r"(r[0]), "=r"(r[1]), "=r"(r[2]), "=r"(r[3]) : "r"(addr));
}
__device__ __forceinline__ void ldm2(uint32_t* r, uint32_t addr) {
    asm volatile("ldmatrix.sync.aligned.m8n8.x2.shared.b16 {%0,%1}, [%2];"
                 : "=r"(r[0]), "=r"(r[1]) : "r"(addr));
}
__device__ __forceinline__ void mma16816(float* c, const uint32_t* a, const uint32_t* b) {
    asm volatile(
        "mma.sync.aligned.m16n8k16.row.col.f32.bf16.bf16.f32 "
        "{%0,%1,%2,%3}, {%4,%5,%6,%7}, {%8,%9}, {%0,%1,%2,%3};"
        : "+f"(c[0]), "+f"(c[1]), "+f"(c[2]), "+f"(c[3])
        : "r"(a[0]), "r"(a[1]), "r"(a[2]), "r"(a[3]), "r"(b[0]), "r"(b[1]));
}

__global__ void __launch_bounds__(512, 1)
tc_gemm_kernel(const float* __restrict__ X, const float* __restrict__ W) {
    extern __shared__ char smem[];
    __nv_bfloat16* As = (__nv_bfloat16*)smem;                  // [128][AST] (hi | lo halves)
    __nv_bfloat16* Bs = (__nv_bfloat16*)(smem + SM_A_BYTES);   // [144][AST]

    int tid = threadIdx.x;          // 512
    int row0 = blockIdx.x * 128;

    // ---- B prologue: pure uint4 copy from precomputed g_wb ----
    for (int i = tid; i < GN * 32; i += 512) {
        int c = i >> 5, q = i & 31;
        uint4 v = ((const uint4*)(g_wb + c * 256))[q];
        *(uint4*)((char*)Bs + c * (AST * 2) + q * 16) = v;
    }
    // ---- A prologue: fp32 -> bf16 hi/lo split in-flight ----
    for (int i = tid; i < 128 * 32; i += 512) {
        int r = i >> 5, q = i & 31;
        int k = q * 4;
        int gr = row0 + r;
        float4 v = make_float4(0.f, 0.f, 0.f, 0.f);
        if (gr < NN) v = *(const float4*)(X + gr * FEAT + k);
        __nv_bfloat16 h0, h1, h2, h3, l0, l1, l2, l3;
        split_bf16(v.x, h0, l0); split_bf16(v.y, h1, l1);
        split_bf16(v.z, h2, l2); split_bf16(v.w, h3, l3);
        __nv_bfloat16* row = As + r * AST;
        *(__nv_bfloat162*)(row + k)           = __nv_bfloat162(h0, h1);
        *(__nv_bfloat162*)(row + k + 2)       = __nv_bfloat162(h2, h3);
        *(__nv_bfloat162*)(row + 128 + k)     = __nv_bfloat162(l0, l1);
        *(__nv_bfloat162*)(row + 128 + k + 2) = __nv_bfloat162(l2, l3);
    }
    __syncthreads();

    // ---- mainloop: 16 warps = 8(M) x 2(N); warp tile 16 x 72 ----
    int wid = tid >> 5, lane = tid & 31;
    int warp_m = wid & 7;
    int warp_n = wid >> 3;
    int m_base = warp_m * 16;
    int n_base = warp_n * 72;

    uint32_t sb = smem_u32(smem);
    uint32_t a_base = sb + (uint32_t)(m_base + (lane & 15)) * (AST * 2)
                         + (uint32_t)((lane >> 4) << 3) * 2;
    uint32_t b_base = sb + SM_A_BYTES
                         + (uint32_t)(n_base + (lane & 7)) * (AST * 2)
                         + (uint32_t)(((lane >> 3) & 1) << 3) * 2;

    float c[9][4];
    #pragma unroll
    for (int j = 0; j < 9; j++)
        #pragma unroll
        for (int q = 0; q < 4; q++) c[j][q] = 0.f;

    // pass 0: A hi x B hi; pass 1: A lo x B hi; pass 2: A hi x B lo
    #pragma unroll
    for (int p = 0; p < 3; ++p) {
        uint32_t aseg = (p == 1) ? 256u : 0u;   // 128 halves = 256 bytes
        uint32_t bseg = (p == 2) ? 256u : 0u;
        #pragma unroll
        for (int ks = 0; ks < 8; ++ks) {
            uint32_t a[4];
            ldm4(a, a_base + aseg + (uint32_t)ks * 32);
            uint32_t b[9][2];
            #pragma unroll
            for (int j = 0; j < 9; ++j)
                ldm2(b[j], b_base + bseg + (uint32_t)ks * 32 + (uint32_t)j * 8 * (AST * 2));
            #pragma unroll
            for (int j = 0; j < 9; ++j)
                mma16816(c[j], a, b[j]);
        }
    }

    // ---- epilogue: direct register -> global ----
    int r_lane = lane >> 2;
    int c_lane = (lane & 3) * 2;
    int gr0 = row0 + m_base + r_lane;
    int gr1 = gr0 + 8;
    #pragma unroll
    for (int j = 0; j < 9; ++j) {
        int nc = n_base + j * 8 + c_lane;
        float v00 = c[j][0], v01 = c[j][1];
        float v10 = c[j][2], v11 = c[j][3];
        if (nc < 128) {
            if (gr0 < NN) {
                __half2 p = __halves2half2(__float2half_rn(v00), __float2half_rn(v01));
                *(__half2*)(g_h + gr0 * 128 + nc) = p;
            }
            if (gr1 < NN) {
                __half2 p = __halves2half2(__float2half_rn(v10), __float2half_rn(v11));
                *(__half2*)(g_h + gr1 * 128 + nc) = p;
            }
        } else {
            int cc = nc - 128;   // 0..15, even
            if (cc < 8) {
                if (gr0 < NN) { g_as[gr0 * 8 + cc] = v00; g_as[gr0 * 8 + cc + 1] = v01; }
                if (gr1 < NN) { g_as[gr1 * 8 + cc] = v10; g_as[gr1 * 8 + cc + 1] = v11; }
            } else {
                int dd = cc - 8;
                if (gr0 < NN) { g_ad[gr0 * 8 + dd] = v00; g_ad[gr0 * 8 + dd + 1] = v01; }
                if (gr1 < NN) { g_ad[gr1 * 8 + dd] = v10; g_ad[gr1 * 8 + dd + 1] = v11; }
            }
        }
    }
}

// ---------------- fused GAT aggregation: warp per dst node (fp16 gather) -----
__global__ void msg_kernel(const float* __restrict__ bias, float* __restrict__ out) {
    int gwarp = (blockIdx.x * blockDim.x + threadIdx.x) >> 5;
    int lane = threadIdx.x & 31;
    if (gwarp >= NN) return;
    int d = gwarp;
    int head = lane >> 2;
    float ad_h = g_ad[d * 8 + head];
    int beg = g_off[d], end = g_off[d + 1];
    int col = lane << 2;

    float4 acc = make_float4(0.f, 0.f, 0.f, 0.f);
    float ssum = 0.f;
    for (int i = beg; i < end; ++i) {
        int s = g_csr[i];
        float as_h = __ldg(&g_as[s * 8 + head]);
        float v = as_h + ad_h;
        v = (v > 0.f) ? v : 0.2f * v;
        float e = __expf(v);
        uint2 raw = *(const uint2*)(g_h + s * 128 + col);
        float2 f0 = __half22float2(*(__half2*)&raw.x);
        float2 f1 = __half22float2(*(__half2*)&raw.y);
        acc.x += e * f0.x;
        acc.y += e * f0.y;
        acc.z += e * f1.x;
        acc.w += e * f1.y;
        ssum += e;
    }
    float inv = 1.f / (ssum + 1e-16f);
    float4 bb = *(const float4*)(bias + col);
    float4 o;
    float t;
    t = acc.x * inv + bb.x; o.x = (t > 0.f) ? t : expm1f(t);
    t = acc.y * inv + bb.y; o.y = (t > 0.f) ? t : expm1f(t);
    t = acc.z * inv + bb.z; o.z = (t > 0.f) ? t : expm1f(t);
    t = acc.w * inv + bb.w; o.w = (t > 0.f) ? t : expm1f(t);
    *(float4*)(out + d * 128 + col) = o;
}

// ---------------- launch ----------------
extern "C" void kernel_launch(void* const* d_in, const int* in_sizes, int n_in,
                              void* d_out, int out_size) {
    const float* x   = (const float*)d_in[0];
    const int*   ei  = (const int*)  d_in[1];
    const float* W1  = (const float*)d_in[2];
    const float* as1 = (const float*)d_in[3];
    const float* ad1 = (const float*)d_in[4];
    const float* b1  = (const float*)d_in[5];
    const float* W2  = (const float*)d_in[6];
    const float* as2 = (const float*)d_in[7];
    const float* ad2 = (const float*)d_in[8];
    const float* b2  = (const float*)d_in[9];
    float* out = (float*)d_out;

    cudaFuncSetAttribute(tc_gemm_kernel,
                         cudaFuncAttributeMaxDynamicSharedMemorySize, TCG_SMEM);

    void* p_x2 = nullptr;
    cudaGetSymbolAddress(&p_x2, g_x2);
    float* x2 = (float*)p_x2;

    int gemm_grid = (NN + 127) / 128;         // 391
    int msg_grid  = (NN * 32 + 255) / 256;
    int ws_grid   = (GN * 128 + 255) / 256;

    // layer 1  (tc_gemm is 4th launch -> ncu capture target)
    wa_kernel     <<<1, 128>>>(W1, as1, ad1);                 // 1
    wsplit_kernel <<<ws_grid, 256>>>(W1);                     // 2
    zero_kernel   <<<(NN + 255) / 256, 256>>>();              // 3
    tc_gemm_kernel<<<gemm_grid, 512, TCG_SMEM>>>(x, W1);      // 4 <- ncu
    count_kernel  <<<(E_TOT + 255) / 256, 256>>>(ei);         // 5
    scan_kernel   <<<1, 1024>>>();                            // 6
    scatter_kernel<<<(E_TOT + 255) / 256, 256>>>(ei);         // 7
    msg_kernel    <<<msg_grid, 256>>>(b1, x2);                // 8

    // layer 2
    wa_kernel     <<<1, 128>>>(W2, as2, ad2);                 // 9
    wsplit_kernel <<<ws_grid, 256>>>(W2);                     // 10
    tc_gemm_kernel<<<gemm_grid, 512, TCG_SMEM>>>(x2, W2);     // 11
    msg_kernel    <<<msg_grid, 256>>>(b2, out);               // 12
}

// round 10
// speedup vs baseline: 1.4163x; 1.0802x over previous
#include <cuda_runtime.h>
#include <cuda_fp16.h>
#include <cuda_bf16.h>
#include <math.h>
#include <cstdint>

#define NN      50000
#define E_BASE  800000
#define E_TOT   850000   // + self loops
#define FEAT    128
#define HID     128
#define NHEAD   8
#define GN      144      // GEMM output cols: 128 h + 8 alpha_src + 8 alpha_dst

// ---------------- scratch (device globals; no allocation) ----------------
__device__ __half        g_h [NN * HID];   // fp16 gather table
__device__ float         g_x2[NN * HID];   // layer-1 output (fp32)
__device__ float         g_as[NN * NHEAD];
__device__ float         g_ad[NN * NHEAD];
__device__ __nv_bfloat16 g_wb[GN * 256];   // W^T ext, [c][k]: k 0..127 hi, 128..255 lo
__device__ int           g_cnt[NN];
__device__ int           g_off[NN + 1];
__device__ int           g_rank[E_TOT];
__device__ int           g_csr[E_TOT];

// ---------------- CSR build ----------------
__global__ void count_kernel(const int* __restrict__ ei) {
    int i = blockIdx.x * blockDim.x + threadIdx.x;
    if (i >= E_TOT) return;
    int d = (i < E_BASE) ? ei[E_BASE + i] : (i - E_BASE);
    g_rank[i] = atomicAdd(&g_cnt[d], 1);
}
#define SCAN_CHUNK 49
__global__ void scan_kernel() {
    __shared__ int warp_sums[32];
    int t = threadIdx.x, lane = t & 31, w = t >> 5;
    int base = t * SCAN_CHUNK;
    int local = 0;
    #pragma unroll 7
    for (int j = 0; j < SCAN_CHUNK; ++j) { int i = base + j; if (i < NN) local += g_cnt[i]; }
    int x = local;
    #pragma unroll
    for (int o = 1; o < 32; o <<= 1) { int y = __shfl_up_sync(~0u, x, o); if (lane >= o) x += y; }
    if (lane == 31) warp_sums[w] = x;
    __syncthreads();
    if (w == 0) {
        int s = warp_sums[lane];
        #pragma unroll
        for (int o = 1; o < 32; o <<= 1) { int y = __shfl_up_sync(~0u, s, o); if (lane >= o) s += y; }
        warp_sums[lane] = s;
    }
    __syncthreads();
    int excl = x - local + ((w > 0) ? warp_sums[w - 1] : 0);
    int run = excl;
    #pragma unroll 7
    for (int j = 0; j < SCAN_CHUNK; ++j) { int i = base + j; if (i < NN) { g_off[i] = run; run += g_cnt[i]; } }
    if (t == 1023) g_off[NN] = run;
}
__global__ void scatter_kernel(const int* __restrict__ ei) {
    int i = blockIdx.x * blockDim.x + threadIdx.x;
    if (i >= E_TOT) return;
    int s, d;
    if (i < E_BASE) { s = ei[i]; d = ei[E_BASE + i]; }
    else            { s = d = i - E_BASE; }
    g_csr[g_off[d] + g_rank[i]] = s;
}

// ---------------- W^T extended hi/lo table (wa folded in) ----------------
__device__ __forceinline__ void split_bf16(float v, __nv_bfloat16& hi, __nv_bfloat16& lo) {
    hi = __float2bfloat16(v);
    lo = __float2bfloat16(v - __bfloat162float(hi));
}
__global__ void wsplit_kernel(const float* __restrict__ W,
                              const float* __restrict__ a_src,
                              const float* __restrict__ a_dst) {
    int i = blockIdx.x * blockDim.x + threadIdx.x;   // GN*128
    if (i >= GN * 128) return;
    int c = i >> 7, k = i & 127;
    float v;
    if (c < 128) {
        v = W[k * 128 + c];
    } else {
        int j = c - 128;                 // 0..15
        int h = j & 7;
        const float* a = (j < 8) ? a_src : a_dst;
        float s = 0.f;
        #pragma unroll
        for (int c2 = 0; c2 < 16; c2++) s += W[k * 128 + h * 16 + c2] * a[h * 16 + c2];
        v = s;
    }
    __nv_bfloat16 hi, lo;
    split_bf16(v, hi, lo);
    g_wb[c * 256 + k]       = hi;
    g_wb[c * 256 + 128 + k] = lo;
}

// ---------------- tensor-core GEMM via mma.sync (arch-portable HMMA) --------
// C[128 x 144] = x @ W_ext, ~fp32 precision: hi*hi + lo*hi + hi*lo.
#define AST 264                        // smem stride in halves (528 B)
#define ROWB (AST * 2)                 // row stride bytes
#define SM_A_BYTES (128 * ROWB)        // 67584
#define SM_B_BYTES (GN  * ROWB)        // 76032
#define TCG_SMEM   (SM_A_BYTES + SM_B_BYTES)   // 143616 B

__device__ __forceinline__ uint32_t smem_u32(const void* p) {
    uint32_t a;
    asm("{ .reg .u64 t; cvta.to.shared.u64 t, %1; cvt.u32.u64 %0, t; }" : "=r"(a) : "l"(p));
    return a;
}
__device__ __forceinline__ void ldm4(uint32_t* r, uint32_t addr) {
    asm volatile("ldmatrix.sync.aligned.m8n8.x4.shared.b16 {%0,%1,%2,%3}, [%4];"
                 : "=r"(r[0]), "=r"(r[1]), "=r"(r[2]), "=r"(r[3]) : "r"(addr));
}
__device__ __forceinline__ void ldm2(uint32_t* r, uint32_t addr) {
    asm volatile("ldmatrix.sync.aligned.m8n8.x2.shared.b16 {%0,%1}, [%2];"
                 : "=r"(r[0]), "=r"(r[1]) : "r"(addr));
}
__device__ __forceinline__ void mma16816(float* c, const uint32_t* a, const uint32_t* b) {
    asm volatile(
        "mma.sync.aligned.m16n8k16.row.col.f32.bf16.bf16.f32 "
        "{%0,%1,%2,%3}, {%4,%5,%6,%7}, {%8,%9}, {%0,%1,%2,%3};"
        : "+f"(c[0]), "+f"(c[1]), "+f"(c[2]), "+f"(c[3])
        : "r"(a[0]), "r"(a[1]), "r"(a[2]), "r"(a[3]), "r"(b[0]), "r"(b[1]));
}

__global__ void __launch_bounds__(512, 1)
tc_gemm_kernel(const float* __restrict__ X, const float* __restrict__ W) {
    extern __shared__ char smem[];
    __nv_bfloat16* As = (__nv_bfloat16*)smem;                  // [128][AST] (hi | lo halves)
    __nv_bfloat16* Bs = (__nv_bfloat16*)(smem + SM_A_BYTES);   // [144][AST]

    int tid = threadIdx.x;          // 512
    int row0 = blockIdx.x * 128;

    // ---- B prologue: pure uint4 copy from precomputed g_wb ----
    for (int i = tid; i < GN * 32; i += 512) {
        int c = i >> 5, q = i & 31;
        uint4 v = ((const uint4*)(g_wb + c * 256))[q];
        *(uint4*)((char*)Bs + c * ROWB + q * 16) = v;
    }
    // ---- A prologue: fp32 -> bf16 hi/lo split in-flight ----
    for (int i = tid; i < 128 * 32; i += 512) {
        int r = i >> 5, q = i & 31;
        int k = q * 4;
        int gr = row0 + r;
        float4 v = make_float4(0.f, 0.f, 0.f, 0.f);
        if (gr < NN) v = *(const float4*)(X + gr * FEAT + k);
        __nv_bfloat16 h0, h1, h2, h3, l0, l1, l2, l3;
        split_bf16(v.x, h0, l0); split_bf16(v.y, h1, l1);
        split_bf16(v.z, h2, l2); split_bf16(v.w, h3, l3);
        __nv_bfloat16* row = As + r * AST;
        *(__nv_bfloat162*)(row + k)           = __nv_bfloat162(h0, h1);
        *(__nv_bfloat162*)(row + k + 2)       = __nv_bfloat162(h2, h3);
        *(__nv_bfloat162*)(row + 128 + k)     = __nv_bfloat162(l0, l1);
        *(__nv_bfloat162*)(row + 128 + k + 2) = __nv_bfloat162(l2, l3);
    }
    __syncthreads();

    // ---- mainloop: 16 warps = 8(M) x 2(N); warp tile 16 x 72 ----
    int wid = tid >> 5, lane = tid & 31;
    int warp_m = wid & 7;
    int warp_n = wid >> 3;
    int m_base = warp_m * 16;
    int n_base = warp_n * 72;

    uint32_t sb = smem_u32(smem);
    uint32_t a_base = sb + (uint32_t)(m_base + (lane & 15)) * ROWB
                         + (uint32_t)((lane >> 4) << 4);           // 8 halves = 16 B
    // quad-B address: lanes grouped g=lane>>3; g0:(j,k0) g1:(j,k8) g2:(j+1,k0) g3:(j+1,k8)
    uint32_t bq_base = sb + SM_A_BYTES
                          + (uint32_t)(n_base + (((lane >> 4) & 1) << 3) + (lane & 7)) * ROWB
                          + (uint32_t)(((lane >> 3) & 1) << 4);
    // pair-B address for the 9th tile (j=8): lanes 0-7 rows, lanes 8-15 k-half
    uint32_t b2_base = sb + SM_A_BYTES
                          + (uint32_t)(n_base + 64 + (lane & 7)) * ROWB
                          + (uint32_t)(((lane >> 3) & 1) << 4);

    float c[9][4];
    #pragma unroll
    for (int j = 0; j < 9; j++)
        #pragma unroll
        for (int q = 0; q < 4; q++) c[j][q] = 0.f;

    // fused pass 0+1: (A_hi + A_lo) x B_hi — B frags loaded once per ks
    #pragma unroll
    for (int ks = 0; ks < 8; ++ks) {
        uint32_t ko = (uint32_t)ks * 32;
        uint32_t b[9][2];
        #pragma unroll
        for (int jp = 0; jp < 4; ++jp)
            ldm4(&b[jp * 2][0], bq_base + ko + (uint32_t)jp * 16 * ROWB);
        ldm2(b[8], b2_base + ko);
        uint32_t ah[4], al[4];
        ldm4(ah, a_base + ko);
        ldm4(al, a_base + ko + 256);
        #pragma unroll
        for (int j = 0; j < 9; ++j) mma16816(c[j], ah, b[j]);
        #pragma unroll
        for (int j = 0; j < 9; ++j) mma16816(c[j], al, b[j]);
    }
    // pass 2: A_hi x B_lo
    #pragma unroll
    for (int ks = 0; ks < 8; ++ks) {
        uint32_t ko = (uint32_t)ks * 32 + 256;   // B lo segment
        uint32_t b[9][2];
        #pragma unroll
        for (int jp = 0; jp < 4; ++jp)
            ldm4(&b[jp * 2][0], bq_base + ko + (uint32_t)jp * 16 * ROWB);
        ldm2(b[8], b2_base + ko);
        uint32_t ah[4];
        ldm4(ah, a_base + (uint32_t)ks * 32);
        #pragma unroll
        for (int j = 0; j < 9; ++j) mma16816(c[j], ah, b[j]);
    }

    // ---- epilogue: direct register -> global ----
    int r_lane = lane >> 2;
    int c_lane = (lane & 3) * 2;
    int gr0 = row0 + m_base + r_lane;
    int gr1 = gr0 + 8;
    #pragma unroll
    for (int j = 0; j < 9; ++j) {
        int nc = n_base + j * 8 + c_lane;
        float v00 = c[j][0], v01 = c[j][1];
        float v10 = c[j][2], v11 = c[j][3];
        if (nc < 128) {
            if (gr0 < NN) {
                __half2 p = __halves2half2(__float2half_rn(v00), __float2half_rn(v01));
                *(__half2*)(g_h + gr0 * 128 + nc) = p;
            }
            if (gr1 < NN) {
                __half2 p = __halves2half2(__float2half_rn(v10), __float2half_rn(v11));
                *(__half2*)(g_h + gr1 * 128 + nc) = p;
            }
        } else {
            int cc = nc - 128;   // 0..15, even
            if (cc < 8) {
                if (gr0 < NN) { g_as[gr0 * 8 + cc] = v00; g_as[gr0 * 8 + cc + 1] = v01; }
                if (gr1 < NN) { g_as[gr1 * 8 + cc] = v10; g_as[gr1 * 8 + cc + 1] = v11; }
            } else {
                int dd = cc - 8;
                if (gr0 < NN) { g_ad[gr0 * 8 + dd] = v00; g_ad[gr0 * 8 + dd + 1] = v01; }
                if (gr1 < NN) { g_ad[gr1 * 8 + dd] = v10; g_ad[gr1 * 8 + dd + 1] = v11; }
            }
        }
    }
}

// ---------------- fused GAT aggregation: warp per dst node (fp16 gather) -----
__global__ void msg_kernel(const float* __restrict__ bias, float* __restrict__ out) {
    int gwarp = (blockIdx.x * blockDim.x + threadIdx.x) >> 5;
    int lane = threadIdx.x & 31;
    if (gwarp >= NN) return;
    int d = gwarp;
    int head = lane >> 2;
    float ad_h = g_ad[d * 8 + head];
    int beg = g_off[d], end = g_off[d + 1];
    int col = lane << 2;

    float4 acc = make_float4(0.f, 0.f, 0.f, 0.f);
    float ssum = 0.f;
    for (int i = beg; i < end; ++i) {
        int s = g_csr[i];
        float as_h = __ldg(&g_as[s * 8 + head]);
        float v = as_h + ad_h;
        v = (v > 0.f) ? v : 0.2f * v;
        float e = __expf(v);
        uint2 raw = *(const uint2*)(g_h + s * 128 + col);
        float2 f0 = __half22float2(*(__half2*)&raw.x);
        float2 f1 = __half22float2(*(__half2*)&raw.y);
        acc.x += e * f0.x;
        acc.y += e * f0.y;
        acc.z += e * f1.x;
        acc.w += e * f1.y;
        ssum += e;
    }
    float inv = 1.f / (ssum + 1e-16f);
    float4 bb = *(const float4*)(bias + col);
    float4 o;
    float t;
    t = acc.x * inv + bb.x; o.x = (t > 0.f) ? t : expm1f(t);
    t = acc.y * inv + bb.y; o.y = (t > 0.f) ? t : expm1f(t);
    t = acc.z * inv + bb.z; o.z = (t > 0.f) ? t : expm1f(t);
    t = acc.w * inv + bb.w; o.w = (t > 0.f) ? t : expm1f(t);
    *(float4*)(out + d * 128 + col) = o;
}

// ---------------- launch ----------------
extern "C" void kernel_launch(void* const* d_in, const int* in_sizes, int n_in,
                              void* d_out, int out_size) {
    const float* x   = (const float*)d_in[0];
    const int*   ei  = (const int*)  d_in[1];
    const float* W1  = (const float*)d_in[2];
    const float* as1 = (const float*)d_in[3];
    const float* ad1 = (const float*)d_in[4];
    const float* b1  = (const float*)d_in[5];
    const float* W2  = (const float*)d_in[6];
    const float* as2 = (const float*)d_in[7];
    const float* ad2 = (const float*)d_in[8];
    const float* b2  = (const float*)d_in[9];
    float* out = (float*)d_out;

    cudaFuncSetAttribute(tc_gemm_kernel,
                         cudaFuncAttributeMaxDynamicSharedMemorySize, TCG_SMEM);

    void *p_x2, *p_cnt;
    cudaGetSymbolAddress(&p_x2,  g_x2);
    cudaGetSymbolAddress(&p_cnt, g_cnt);
    float* x2 = (float*)p_x2;

    int gemm_grid = (NN + 127) / 128;         // 391
    int msg_grid  = (NN * 32 + 255) / 256;
    int ws_grid   = (GN * 128 + 255) / 256;

    // layer 1  (tc_gemm is 4th kernel launch -> ncu capture target)
    wsplit_kernel <<<ws_grid, 256>>>(W1, as1, ad1);           // 1
    cudaMemsetAsync(p_cnt, 0, NN * sizeof(int));              // (not a kernel)
    count_kernel  <<<(E_TOT + 255) / 256, 256>>>(ei);         // 2
    scan_kernel   <<<1, 1024>>>();                            // 3
    tc_gemm_kernel<<<gemm_grid, 512, TCG_SMEM>>>(x, W1);      // 4 <- ncu
    scatter_kernel<<<(E_TOT + 255) / 256, 256>>>(ei);         // 5
    msg_kernel    <<<msg_grid, 256>>>(b1, x2);                // 6

    // layer 2
    wsplit_kernel <<<ws_grid, 256>>>(W2, as2, ad2);           // 7
    tc_gemm_kernel<<<gemm_grid, 512, TCG_SMEM>>>(x2, W2);     // 8
    msg_kernel    <<<msg_grid, 256>>>(b2, out);               // 9
}